// round 7
// baseline (speedup 1.0000x reference)
#include <cuda_runtime.h>

#define BB   8
#define QQ   256
#define KK   1024
#define DD   256
#define HH   128
#define DVV  128
#define LOG2E 1.44269504088896340736f

// Scratch (allocation-free device globals). Ek4 padded by 2*KK float4 rows so
// the software-pipeline tail prefetch never reads out of bounds.
__device__ float g_Eq [BB * QQ * HH];                    // [b][q][h]
__device__ float g_Ek4[BB * (HH/4) * KK * 4 + 8 * KK];   // [b][h/4][k][4]

__device__ __forceinline__ float frcp(float x) {
    float r; asm("rcp.approx.f32 %0, %1;" : "=f"(r) : "f"(x)); return r;
}
__device__ __forceinline__ float fex2(float x) {
    float r; asm("ex2.approx.f32 %0, %1;" : "=f"(r) : "f"(x)); return r;
}

// ---------------------------------------------------------------------------
// Kernel 1: merged projection + exp. 16 rows/block, thread = column h.
// W in native [d][h] layout (coalesced), depth-1 prefetch (R5 version).
// ---------------------------------------------------------------------------
#define PR 16
__global__ __launch_bounds__(128)
void proj_kernel(const float* __restrict__ Q, const float* __restrict__ Kx,
                 const float* __restrict__ Wq, const float* __restrict__ Wk) {
    __shared__ __align__(16) float xs[PR][DD];     // 16 input rows (16 KB)
    __shared__ float es[HH][PR + 1];               // padded transpose buffer
    int blk  = blockIdx.x;
    bool isK = blk >= (BB * QQ) / PR;              // >= 128
    int rowbase = isK ? (blk - (BB * QQ) / PR) * PR : blk * PR;
    const float* X = isK ? Kx : Q;
    const float* W = isK ? Wk : Wq;
    int tid = threadIdx.x;                          // 0..127 (= h)

    {   // coalesced float4 row load
        const float4* Xp = (const float4*)(X + (size_t)rowbase * DD);
        float4* xsp = (float4*)xs;
        for (int i = tid; i < PR * DD / 4; i += 128) xsp[i] = Xp[i];
    }
    __syncthreads();

    float acc[PR];
#pragma unroll
    for (int r = 0; r < PR; r++) acc[r] = 0.f;

    const float* Wp = W + tid;
    float w0 = Wp[0 * HH], w1 = Wp[1 * HH], w2 = Wp[2 * HH], w3 = Wp[3 * HH];
    for (int d4 = 0; d4 < DD / 4; d4++) {
        float c0 = w0, c1 = w1, c2 = w2, c3 = w3;
        if (d4 + 1 < DD / 4) {                     // prefetch next W quad
            const float* Wn = Wp + (d4 + 1) * 4 * HH;
            w0 = Wn[0 * HH]; w1 = Wn[1 * HH]; w2 = Wn[2 * HH]; w3 = Wn[3 * HH];
        }
        int d = d4 * 4;
#pragma unroll
        for (int r = 0; r < PR; r++) {
            float4 x = *(const float4*)&xs[r][d];  // broadcast LDS.128
            acc[r] = fmaf(x.x, c0, acc[r]);
            acc[r] = fmaf(x.y, c1, acc[r]);
            acc[r] = fmaf(x.z, c2, acc[r]);
            acc[r] = fmaf(x.w, c3, acc[r]);
        }
    }

    if (!isK) {
#pragma unroll
        for (int r = 0; r < PR; r++)
            g_Eq[(rowbase + r) * HH + tid] = fex2(acc[r] * (2.0f * LOG2E));
    } else {
#pragma unroll
        for (int r = 0; r < PR; r++)
            es[tid][r] = fex2(acc[r] * (2.0f * LOG2E));
        __syncthreads();
        int b  = rowbase >> 10;
        int k0 = rowbase & 1023;
        for (int i = tid; i < HH * PR; i += 128) {
            int hq = i >> 6;              // 64 = PR*4 elements per h-quad
            int r  = (i >> 2) & (PR - 1);
            int h2 = i & 3;
            g_Ek4[(((size_t)b * (HH/4) + hq) * KK + k0 + r) * 4 + h2]
                = es[hq * 4 + h2][r];
        }
    }
}

// ---------------------------------------------------------------------------
// Kernel 2: fused scores + exp + denom + attn@V.
// Block = (b, tile of 2 q-rows), 1024 blocks, 256 threads, 2 k per thread.
//   s(q,k) = sum_h (-2 w_h) * rcp(1 + Eq*Ek)   (wsum cancels in softmax)
// |s| small -> exp without max subtraction is fp32-safe.
// MOV-free depth-2 pipeline over interleaved Ek quads (pointer increment,
// named A/B buffer sets), q=2 state budget for occupancy.
// ---------------------------------------------------------------------------
// One h-quad (4 h values in c = one LDG.128) for one k, accumulating both q:
#define ONEK2(c, e0, e1, e2, e3, wv, acc0, acc1) do {              \
    float E1_, E2_, num_;                                          \
    E1_ = fmaf((c).x, (e0).x, 1.f);                                \
    E2_ = fmaf((c).y, (e1).x, 1.f);                                \
    num_ = fmaf((wv).x, E2_, (wv).y * E1_);                        \
    (acc0) = fmaf(num_, frcp(E1_ * E2_), (acc0));                  \
    E1_ = fmaf((c).x, (e0).y, 1.f);                                \
    E2_ = fmaf((c).y, (e1).y, 1.f);                                \
    num_ = fmaf((wv).x, E2_, (wv).y * E1_);                        \
    (acc1) = fmaf(num_, frcp(E1_ * E2_), (acc1));                  \
    E1_ = fmaf((c).z, (e2).x, 1.f);                                \
    E2_ = fmaf((c).w, (e3).x, 1.f);                                \
    num_ = fmaf((wv).z, E2_, (wv).w * E1_);                        \
    (acc0) = fmaf(num_, frcp(E1_ * E2_), (acc0));                  \
    E1_ = fmaf((c).z, (e2).y, 1.f);                                \
    E2_ = fmaf((c).w, (e3).y, 1.f);                                \
    num_ = fmaf((wv).z, E2_, (wv).w * E1_);                        \
    (acc1) = fmaf(num_, frcp(E1_ * E2_), (acc1));                  \
} while (0)

#define BODY2(ca, cb, hh) do {                                     \
    float2 e0_ = s_eq2[(hh)];                                      \
    float2 e1_ = s_eq2[(hh) + 1];                                  \
    float2 e2_ = s_eq2[(hh) + 2];                                  \
    float2 e3_ = s_eq2[(hh) + 3];                                  \
    float4 w_ = *(const float4*)&s_w2[(hh)];                       \
    ONEK2(ca, e0_, e1_, e2_, e3_, w_, a00, a01);                   \
    ONEK2(cb, e0_, e1_, e2_, e3_, w_, a10, a11);                   \
} while (0)

__global__ __launch_bounds__(256, 6)
void attn_kernel(const float* __restrict__ values,
                 const int*   __restrict__ valid_lens,
                 const float* __restrict__ w_v,
                 float*       __restrict__ out) {
    __shared__ __align__(16) float2 s_eq2[HH];         // [h] -> (q0, q1)
    __shared__ __align__(16) float s_w2[HH];           // -2*w_v[h]
    __shared__ __align__(16) float s_scores[KK * 2];   // exp'ed probs [k][q]
    __shared__ __align__(16) float s_part[4][2][DVV];  // [kgroup][q][v]
    __shared__ float s_red[8][2];
    __shared__ float s_rden[2];

    int b  = blockIdx.x & 7;                // interleave batches across SMs
    int q0 = (blockIdx.x >> 3) * 2;
    int tid = threadIdx.x;
    int len = valid_lens[b];

    if (tid < HH) s_w2[tid] = -2.0f * w_v[tid];
    if (tid < 2 * HH) {
        int qq = tid >> 7, h = tid & 127;
        ((float*)&s_eq2[h])[qq] = g_Eq[((b * QQ) + q0 + qq) * HH + h];
    }
    __syncthreads();

    float sum0 = 0.f, sum1 = 0.f;   // denominator partials (q0, q1)

    // ---- main loop: scores + exp (k chunks of 512, 2 k per thread) ----
    for (int kbase = 0; kbase < len; kbase += 512) {
        int k0 = kbase + tid * 2;
        if (k0 < len) {
            float a00 = 0.f, a01 = 0.f;   // k0:   q0, q1
            float a10 = 0.f, a11 = 0.f;   // k0+1: q0, q1
            const float4* pb = (const float4*)g_Ek4
                             + (size_t)b * (HH / 4) * KK + k0;
            float4 Aa = pb[0],  Ab = pb[1];       // quad hq
            float4 Ba = pb[KK], Bb = pb[KK + 1];  // quad hq+1
            const float4* pld = pb + 2 * KK;
#pragma unroll 4
            for (int hq = 0; hq < HH / 4; hq += 2) {
                int h = hq * 4;
                BODY2(Aa, Ab, h);
                Aa = pld[0]; Ab = pld[1]; pld += KK;
                BODY2(Ba, Bb, h + 4);
                Ba = pld[0]; Bb = pld[1]; pld += KK;
            }
            float p00 = fex2(a00 * LOG2E);
            float p01 = fex2(a01 * LOG2E);
            float p10 = fex2(a10 * LOG2E);
            float p11 = fex2(a11 * LOG2E);
            *(float4*)&s_scores[k0 * 2] = make_float4(p00, p01, p10, p11);
            sum0 += p00; sum1 += p01;
            if (k0 + 1 < len) { sum0 += p10; sum1 += p11; }
        }
    }

    // ---- denominator reduction ----
    int warp = tid >> 5, lane = tid & 31;
    for (int o = 16; o > 0; o >>= 1) {
        sum0 += __shfl_xor_sync(0xffffffffu, sum0, o);
        sum1 += __shfl_xor_sync(0xffffffffu, sum1, o);
    }
    if (lane == 0) { s_red[warp][0] = sum0; s_red[warp][1] = sum1; }
    __syncthreads();
    if (tid < 2) {
        float s = 0.f;
        for (int w = 0; w < 8; w++) s += s_red[w][tid];
        s_rden[tid] = frcp(s);
    }
    __syncthreads();

    // ---- attn @ V  (k split into 4 strided groups, reduce via smem) ----
    int g = tid >> 6;          // k-group
    int l = tid & 63;          // v pair index: v0 = 2*l
    float2 c0 = make_float2(0.f, 0.f);
    float2 c1 = make_float2(0.f, 0.f);
    const float2* Vp = (const float2*)(values + (size_t)b * KK * DVV) + l;
#pragma unroll 4
    for (int k = g; k < len; k += 4) {
        float2 p = *(const float2*)&s_scores[k * 2];
        float2 v = Vp[k * (DVV / 2)];
        c0.x = fmaf(p.x, v.x, c0.x); c0.y = fmaf(p.x, v.y, c0.y);
        c1.x = fmaf(p.y, v.x, c1.x); c1.y = fmaf(p.y, v.y, c1.y);
    }
    *(float2*)&s_part[g][0][2 * l] = c0;
    *(float2*)&s_part[g][1][2 * l] = c1;
    __syncthreads();

    // final combine: 256 outputs (2 q x 128 v), 1 per thread
    {
        int qq = tid >> 7;
        int v  = tid & 127;
        float rd = s_rden[qq];
        float o = s_part[0][qq][v] + s_part[1][qq][v]
                + s_part[2][qq][v] + s_part[3][qq][v];
        out[((size_t)(b * QQ + q0 + qq)) * DVV + v] = o * rd;
    }
}

extern "C" void kernel_launch(void* const* d_in, const int* in_sizes, int n_in,
                              void* d_out, int out_size) {
    const float* queries = (const float*)d_in[0];   // [8,256,256]
    const float* keys    = (const float*)d_in[1];   // [8,1024,256]
    const float* values  = (const float*)d_in[2];   // [8,1024,128]
    const int*   vlens   = (const int*)  d_in[3];   // [8]
    const float* W_q     = (const float*)d_in[4];   // [256,128]
    const float* W_k     = (const float*)d_in[5];   // [256,128]
    const float* w_v     = (const float*)d_in[6];   // [128]
    float* out = (float*)d_out;                     // [8,256,128]

    proj_kernel<<<(BB * QQ + BB * KK) / PR, 128>>>(queries, keys, W_q, W_k);
    attn_kernel<<<BB * (QQ / 2), 256>>>(values, vlens, w_v, out);
}

// round 9
// speedup vs baseline: 1.4551x; 1.4551x over previous
#include <cuda_runtime.h>

#define BB   8
#define QQ   256
#define KK   1024
#define DD   256
#define HH   128
#define DVV  128
#define LOG2E 1.44269504088896340736f

// Scratch (allocation-free: device globals)
__device__ float g_Eq [BB * QQ * HH];        // [b][q][h]   = exp(2*qproj)
__device__ float g_Ek4[BB * (HH/4) * KK * 4];// [b][h/4][k][4] = exp(2*kproj)

__device__ __forceinline__ float frcp(float x) {
    float r; asm("rcp.approx.f32 %0, %1;" : "=f"(r) : "f"(x)); return r;
}
__device__ __forceinline__ float fex2(float x) {
    float r; asm("ex2.approx.f32 %0, %1;" : "=f"(r) : "f"(x)); return r;
}

// ---------------------------------------------------------------------------
// Kernel 1: merged projection + exp. 16 rows per block, thread = column h.
// W read in native [d][h] layout (coalesced), prefetched one quad ahead.
//   blocks [0,128)   : query rows -> g_Eq[row][h]
//   blocks [128,640) : key rows   -> g_Ek4[b][h/4][k][4] (interleaved)
// ---------------------------------------------------------------------------
#define PR 16
__global__ __launch_bounds__(128)
void proj_kernel(const float* __restrict__ Q, const float* __restrict__ Kx,
                 const float* __restrict__ Wq, const float* __restrict__ Wk) {
    __shared__ __align__(16) float xs[PR][DD];     // 16 input rows (16 KB)
    __shared__ float es[HH][PR + 1];               // padded transpose buffer
    int blk  = blockIdx.x;
    bool isK = blk >= (BB * QQ) / PR;              // >= 128
    int rowbase = isK ? (blk - (BB * QQ) / PR) * PR : blk * PR;
    const float* X = isK ? Kx : Q;
    const float* W = isK ? Wk : Wq;
    int tid = threadIdx.x;                          // 0..127 (= h)

    {   // coalesced float4 row load
        const float4* Xp = (const float4*)(X + (size_t)rowbase * DD);
        float4* xsp = (float4*)xs;
        for (int i = tid; i < PR * DD / 4; i += 128) xsp[i] = Xp[i];
    }
    __syncthreads();

    float acc[PR];
#pragma unroll
    for (int r = 0; r < PR; r++) acc[r] = 0.f;

    const float* Wp = W + tid;
    float w0 = Wp[0 * HH], w1 = Wp[1 * HH], w2 = Wp[2 * HH], w3 = Wp[3 * HH];
    for (int d4 = 0; d4 < DD / 4; d4++) {
        float c0 = w0, c1 = w1, c2 = w2, c3 = w3;
        if (d4 + 1 < DD / 4) {                     // prefetch next W quad
            const float* Wn = Wp + (d4 + 1) * 4 * HH;
            w0 = Wn[0 * HH]; w1 = Wn[1 * HH]; w2 = Wn[2 * HH]; w3 = Wn[3 * HH];
        }
        int d = d4 * 4;
#pragma unroll
        for (int r = 0; r < PR; r++) {
            float4 x = *(const float4*)&xs[r][d];  // broadcast LDS.128
            acc[r] = fmaf(x.x, c0, acc[r]);
            acc[r] = fmaf(x.y, c1, acc[r]);
            acc[r] = fmaf(x.z, c2, acc[r]);
            acc[r] = fmaf(x.w, c3, acc[r]);
        }
    }

    if (!isK) {
#pragma unroll
        for (int r = 0; r < PR; r++)
            g_Eq[(rowbase + r) * HH + tid] = fex2(acc[r] * (2.0f * LOG2E));
    } else {
#pragma unroll
        for (int r = 0; r < PR; r++)
            es[tid][r] = fex2(acc[r] * (2.0f * LOG2E));
        __syncthreads();
        int b  = rowbase >> 10;
        int k0 = rowbase & 1023;
        // interleaved store: [hq][k][h%4], consecutive i -> consecutive addr
        for (int i = tid; i < HH * PR; i += 128) {
            int hq = i >> 6;              // 64 = PR*4 elements per h-quad
            int r  = (i >> 2) & (PR - 1);
            int h2 = i & 3;
            g_Ek4[(((size_t)b * (HH/4) + hq) * KK + k0 + r) * 4 + h2]
                = es[hq * 4 + h2][r];
        }
    }
}

// ---------------------------------------------------------------------------
// Kernel 2: fused scores + exp + softmax-denominator + attn@V.
// Block = (b, tile of 2 q-rows), 1024 blocks, 256 threads.
// score (up to the constant wsum, which cancels in softmax):
//   s = sum_h (-2 w_h) * rcp(1 + Eq*Ek)
// |s| <= 2*sum|w_h| (~18) -> exp without max subtraction is fp32-safe.
// exp fused into the score loop; denom accumulated in registers.
// Ek loads: LDG.128 per (4h,k), indexed prefetch depth 2 (R5 structure —
// do NOT convert to pointer-increment form; see R7 regression).
// __launch_bounds__(256,6): regs 48->~40, +1 resident block/SM.
// ---------------------------------------------------------------------------
__global__ __launch_bounds__(256, 6)
void attn_kernel(const float* __restrict__ values,
                 const int*   __restrict__ valid_lens,
                 const float* __restrict__ w_v,
                 float*       __restrict__ out) {
    __shared__ __align__(16) float s_eq[HH][2];        // [h][q]
    __shared__ __align__(16) float s_w2[HH];           // -2*w_v[h]
    __shared__ __align__(16) float s_scores[KK * 2];   // exp'ed probs [k][q]
    __shared__ __align__(16) float s_part[4][2][DVV];  // [kgroup][q][v]
    __shared__ float s_red[8][2];
    __shared__ float s_rden[2];

    int b  = blockIdx.x & 7;
    int q0 = (blockIdx.x >> 3) * 2;
    int tid = threadIdx.x;
    int len = valid_lens[b];

    if (tid < HH) s_w2[tid] = -2.0f * w_v[tid];
    if (tid < 2 * HH) {
        int qq = tid >> 7, h = tid & 127;
        s_eq[h][qq] = g_Eq[((b * QQ) + q0 + qq) * HH + h];
    }
    __syncthreads();

    float sum0 = 0.f, sum1 = 0.f;   // denominator partials (q0, q1)

    // ---- main loop: scores + exp (k chunks of 512, 2 k per thread) ----
    for (int kbase = 0; kbase < len; kbase += 512) {
        int k0 = kbase + tid * 2;
        if (k0 < len) {
            float aA0 = 0.f, aA1 = 0.f, aB0 = 0.f, aB1 = 0.f; // [k][q]
            // float4 view: index = hq*KK + k
            const float4* ek4 = (const float4*)g_Ek4 + (size_t)b * (HH/4) * KK + k0;
            float4 p0a = ek4[0];            // hq=0, k0
            float4 p0b = ek4[1];            // hq=0, k0+1
            float4 p1a = ek4[KK];           // hq=1, k0
            float4 p1b = ek4[KK + 1];       // hq=1, k0+1
#pragma unroll 2
            for (int hq = 0; hq < HH / 4; hq++) {
                float4 ca = p0a, cb = p0b;
                p0a = p1a; p0b = p1b;
                int hn = (hq + 2) & (HH / 4 - 1);     // wrap: harmless reload
                p1a = ek4[(size_t)hn * KK];
                p1b = ek4[(size_t)hn * KK + 1];
                int h = hq * 4;
                float4 eqA = *(const float4*)&s_eq[h][0];     // h,h+1 x q0,q1
                float4 eqB = *(const float4*)&s_eq[h + 2][0]; // h+2,h+3
                float4 w   = *(const float4*)&s_w2[h];
                float E1, E2, num;
                // pair (h, h+1): components .x/.y of ca,cb
                E1 = fmaf(ca.x, eqA.x, 1.f); E2 = fmaf(ca.y, eqA.z, 1.f);
                num = fmaf(w.x, E2, w.y * E1);
                aA0 = fmaf(num, frcp(E1 * E2), aA0);
                E1 = fmaf(ca.x, eqA.y, 1.f); E2 = fmaf(ca.y, eqA.w, 1.f);
                num = fmaf(w.x, E2, w.y * E1);
                aA1 = fmaf(num, frcp(E1 * E2), aA1);
                E1 = fmaf(cb.x, eqA.x, 1.f); E2 = fmaf(cb.y, eqA.z, 1.f);
                num = fmaf(w.x, E2, w.y * E1);
                aB0 = fmaf(num, frcp(E1 * E2), aB0);
                E1 = fmaf(cb.x, eqA.y, 1.f); E2 = fmaf(cb.y, eqA.w, 1.f);
                num = fmaf(w.x, E2, w.y * E1);
                aB1 = fmaf(num, frcp(E1 * E2), aB1);
                // pair (h+2, h+3): components .z/.w
                E1 = fmaf(ca.z, eqB.x, 1.f); E2 = fmaf(ca.w, eqB.z, 1.f);
                num = fmaf(w.z, E2, w.w * E1);
                aA0 = fmaf(num, frcp(E1 * E2), aA0);
                E1 = fmaf(ca.z, eqB.y, 1.f); E2 = fmaf(ca.w, eqB.w, 1.f);
                num = fmaf(w.z, E2, w.w * E1);
                aA1 = fmaf(num, frcp(E1 * E2), aA1);
                E1 = fmaf(cb.z, eqB.x, 1.f); E2 = fmaf(cb.w, eqB.z, 1.f);
                num = fmaf(w.z, E2, w.w * E1);
                aB0 = fmaf(num, frcp(E1 * E2), aB0);
                E1 = fmaf(cb.z, eqB.y, 1.f); E2 = fmaf(cb.w, eqB.w, 1.f);
                num = fmaf(w.z, E2, w.w * E1);
                aB1 = fmaf(num, frcp(E1 * E2), aB1);
            }
            // exp (no max subtraction needed: |score| <= ~18)
            float pA0 = fex2(aA0 * LOG2E);
            float pA1 = fex2(aA1 * LOG2E);
            float pB0 = fex2(aB0 * LOG2E);
            float pB1 = fex2(aB1 * LOG2E);
            *(float4*)&s_scores[k0 * 2] = make_float4(pA0, pA1, pB0, pB1);
            bool two = (k0 + 1 < len);
            if (!two) { pB0 = 0.f; pB1 = 0.f; }   // guard odd len tail
            sum0 += pA0 + pB0;
            sum1 += pA1 + pB1;
        }
    }
    // NOTE: if len is odd, s_scores[len] was written but AV reads only k<len.

    // ---- denominator reduction ----
    int warp = tid >> 5, lane = tid & 31;
    for (int o = 16; o > 0; o >>= 1) {
        sum0 += __shfl_xor_sync(0xffffffffu, sum0, o);
        sum1 += __shfl_xor_sync(0xffffffffu, sum1, o);
    }
    if (lane == 0) { s_red[warp][0] = sum0; s_red[warp][1] = sum1; }
    __syncthreads();
    if (tid < 2) {
        float s = 0.f;
        for (int w = 0; w < 8; w++) s += s_red[w][tid];
        s_rden[tid] = frcp(s);
    }
    __syncthreads();

    // ---- attn @ V  (k split into 4 strided groups, reduce via smem) ----
    int g = tid >> 6;          // k-group
    int l = tid & 63;          // v pair index: v0 = 2*l
    float2 a0 = make_float2(0.f, 0.f);
    float2 a1 = make_float2(0.f, 0.f);
    const float2* Vp = (const float2*)(values + (size_t)b * KK * DVV);
    for (int k = g; k < len; k += 4) {
        float2 p = *(const float2*)&s_scores[k * 2];
        float2 v = Vp[k * (DVV / 2) + l];
        a0.x = fmaf(p.x, v.x, a0.x); a0.y = fmaf(p.x, v.y, a0.y);
        a1.x = fmaf(p.y, v.x, a1.x); a1.y = fmaf(p.y, v.y, a1.y);
    }
    *(float2*)&s_part[g][0][2 * l] = a0;
    *(float2*)&s_part[g][1][2 * l] = a1;
    __syncthreads();

    {
        int qq = tid >> 7;
        int v  = tid & 127;
        float rd = s_rden[qq];
        float o = s_part[0][qq][v] + s_part[1][qq][v]
                + s_part[2][qq][v] + s_part[3][qq][v];
        out[((size_t)(b * QQ + q0 + qq)) * DVV + v] = o * rd;
    }
}

extern "C" void kernel_launch(void* const* d_in, const int* in_sizes, int n_in,
                              void* d_out, int out_size) {
    const float* queries = (const float*)d_in[0];   // [8,256,256]
    const float* keys    = (const float*)d_in[1];   // [8,1024,256]
    const float* values  = (const float*)d_in[2];   // [8,1024,128]
    const int*   vlens   = (const int*)  d_in[3];   // [8]
    const float* W_q     = (const float*)d_in[4];   // [256,128]
    const float* W_k     = (const float*)d_in[5];   // [256,128]
    const float* w_v     = (const float*)d_in[6];   // [128]
    float* out = (float*)d_out;                     // [8,256,128]

    proj_kernel<<<(BB * QQ + BB * KK) / PR, 128>>>(queries, keys, W_q, W_k);
    attn_kernel<<<BB * (QQ / 2), 256>>>(values, vlens, w_v, out);
}

// round 12
// speedup vs baseline: 1.7535x; 1.2050x over previous
#include <cuda_runtime.h>

#define BB   8
#define QQ   256
#define KK   1024
#define DD   256
#define HH   128
#define DVV  128
#define LOG2E 1.44269504088896340736f

// Scratch (allocation-free: device globals)
__device__ float g_Eq [BB * QQ * HH];        // [b][q][h]   = exp(2*qproj)
__device__ float g_Ek4[BB * (HH/4) * KK * 4];// [b][h/4][k][4] = exp(2*kproj)

__device__ __forceinline__ float frcp(float x) {
    float r; asm("rcp.approx.f32 %0, %1;" : "=f"(r) : "f"(x)); return r;
}
__device__ __forceinline__ float fex2(float x) {
    float r; asm("ex2.approx.f32 %0, %1;" : "=f"(r) : "f"(x)); return r;
}

// ---------------------------------------------------------------------------
// Kernel 1: merged projection + exp. 16 rows per block, 256 threads:
// tid&127 = output column h, tid>>7 = row-half (rows half*8 .. half*8+7).
// Both halves issue the same W addresses -> L1 broadcast; occupancy doubles
// vs the 128-thread version (the R5 proj was latency-bound at 36% occ).
//   blocks [0,128)   : query rows -> g_Eq[row][h]
//   blocks [128,640) : key rows   -> g_Ek4[b][h/4][k][4] (interleaved)
// ---------------------------------------------------------------------------
#define PR 16
__global__ __launch_bounds__(256)
void proj_kernel(const float* __restrict__ Q, const float* __restrict__ Kx,
                 const float* __restrict__ Wq, const float* __restrict__ Wk) {
    __shared__ __align__(16) float xs[PR][DD];     // 16 input rows (16 KB)
    __shared__ float es[HH][PR + 1];               // padded transpose buffer
    int blk  = blockIdx.x;
    bool isK = blk >= (BB * QQ) / PR;              // >= 128
    int rowbase = isK ? (blk - (BB * QQ) / PR) * PR : blk * PR;
    const float* X = isK ? Kx : Q;
    const float* W = isK ? Wk : Wq;
    int tid  = threadIdx.x;
    int h    = tid & 127;                          // output column
    int half = tid >> 7;                           // row-half: 0 or 1
    int r0   = half * 8;                           // first of 8 rows

    {   // coalesced float4 row load (256 threads)
        const float4* Xp = (const float4*)(X + (size_t)rowbase * DD);
        float4* xsp = (float4*)xs;
        for (int i = tid; i < PR * DD / 4; i += 256) xsp[i] = Xp[i];
    }
    __syncthreads();

    float acc[8];
#pragma unroll
    for (int r = 0; r < 8; r++) acc[r] = 0.f;

    const float* Wp = W + h;
    float w0 = Wp[0 * HH], w1 = Wp[1 * HH], w2 = Wp[2 * HH], w3 = Wp[3 * HH];
    for (int d4 = 0; d4 < DD / 4; d4++) {
        float c0 = w0, c1 = w1, c2 = w2, c3 = w3;
        if (d4 + 1 < DD / 4) {                     // prefetch next W quad
            const float* Wn = Wp + (d4 + 1) * 4 * HH;
            w0 = Wn[0 * HH]; w1 = Wn[1 * HH]; w2 = Wn[2 * HH]; w3 = Wn[3 * HH];
        }
        int d = d4 * 4;
#pragma unroll
        for (int r = 0; r < 8; r++) {
            float4 x = *(const float4*)&xs[r0 + r][d];  // broadcast LDS.128
            acc[r] = fmaf(x.x, c0, acc[r]);
            acc[r] = fmaf(x.y, c1, acc[r]);
            acc[r] = fmaf(x.z, c2, acc[r]);
            acc[r] = fmaf(x.w, c3, acc[r]);
        }
    }

    if (!isK) {
#pragma unroll
        for (int r = 0; r < 8; r++)
            g_Eq[(rowbase + r0 + r) * HH + h] = fex2(acc[r] * (2.0f * LOG2E));
    } else {
#pragma unroll
        for (int r = 0; r < 8; r++)
            es[h][r0 + r] = fex2(acc[r] * (2.0f * LOG2E));
        __syncthreads();
        int b  = rowbase >> 10;
        int k0 = rowbase & 1023;
        // interleaved store: [hq][k][h%4], consecutive i -> consecutive addr
        for (int i = tid; i < HH * PR; i += 256) {
            int hq = i >> 6;              // 64 = PR*4 elements per h-quad
            int r  = (i >> 2) & (PR - 1);
            int h2 = i & 3;
            g_Ek4[(((size_t)b * (HH/4) + hq) * KK + k0 + r) * 4 + h2]
                = es[hq * 4 + h2][r];
        }
    }
}

// ---------------------------------------------------------------------------
// Kernel 2: fused scores + exp + softmax-denominator + attn@V.
// Block = (b, tile of 2 q-rows), 1024 blocks, 256 threads.
// score (up to the constant wsum, which cancels in softmax):
//   s = sum_h (-2 w_h) * rcp(1 + Eq*Ek)
// |s| <= 2*sum|w_h| (~18) -> exp without max subtraction is fp32-safe.
// Main loop = R5 structure VERBATIM (indexed depth-2 prefetch; every variant
// tried — q=4 tile, pointer-increment pipeline, launch_bounds reg squeeze —
// regressed). AV loop widened: 8 k-groups x 32 lanes, float4 V loads.
// ---------------------------------------------------------------------------
__global__ __launch_bounds__(256)
void attn_kernel(const float* __restrict__ values,
                 const int*   __restrict__ valid_lens,
                 const float* __restrict__ w_v,
                 float*       __restrict__ out) {
    __shared__ __align__(16) float s_eq[HH][2];        // [h][q]
    __shared__ __align__(16) float s_w2[HH];           // -2*w_v[h]
    __shared__ __align__(16) float s_scores[KK * 2];   // exp'ed probs [k][q]
    __shared__ __align__(16) float s_part[8][2][DVV];  // [kgroup][q][v]
    __shared__ float s_red[8][2];
    __shared__ float s_rden[2];

    int b  = blockIdx.x & 7;
    int q0 = (blockIdx.x >> 3) * 2;
    int tid = threadIdx.x;
    int len = valid_lens[b];

    if (tid < HH) s_w2[tid] = -2.0f * w_v[tid];
    if (tid < 2 * HH) {
        int qq = tid >> 7, h = tid & 127;
        s_eq[h][qq] = g_Eq[((b * QQ) + q0 + qq) * HH + h];
    }
    __syncthreads();

    float sum0 = 0.f, sum1 = 0.f;   // denominator partials (q0, q1)

    // ---- main loop: scores + exp (k chunks of 512, 2 k per thread) ----
    for (int kbase = 0; kbase < len; kbase += 512) {
        int k0 = kbase + tid * 2;
        if (k0 < len) {
            float aA0 = 0.f, aA1 = 0.f, aB0 = 0.f, aB1 = 0.f; // [k][q]
            // float4 view: index = hq*KK + k
            const float4* ek4 = (const float4*)g_Ek4 + (size_t)b * (HH/4) * KK + k0;
            float4 p0a = ek4[0];            // hq=0, k0
            float4 p0b = ek4[1];            // hq=0, k0+1
            float4 p1a = ek4[KK];           // hq=1, k0
            float4 p1b = ek4[KK + 1];       // hq=1, k0+1
#pragma unroll 2
            for (int hq = 0; hq < HH / 4; hq++) {
                float4 ca = p0a, cb = p0b;
                p0a = p1a; p0b = p1b;
                int hn = (hq + 2) & (HH / 4 - 1);     // wrap: harmless reload
                p1a = ek4[(size_t)hn * KK];
                p1b = ek4[(size_t)hn * KK + 1];
                int h = hq * 4;
                float4 eqA = *(const float4*)&s_eq[h][0];     // h,h+1 x q0,q1
                float4 eqB = *(const float4*)&s_eq[h + 2][0]; // h+2,h+3
                float4 w   = *(const float4*)&s_w2[h];
                float E1, E2, num;
                // pair (h, h+1): components .x/.y of ca,cb
                E1 = fmaf(ca.x, eqA.x, 1.f); E2 = fmaf(ca.y, eqA.z, 1.f);
                num = fmaf(w.x, E2, w.y * E1);
                aA0 = fmaf(num, frcp(E1 * E2), aA0);
                E1 = fmaf(ca.x, eqA.y, 1.f); E2 = fmaf(ca.y, eqA.w, 1.f);
                num = fmaf(w.x, E2, w.y * E1);
                aA1 = fmaf(num, frcp(E1 * E2), aA1);
                E1 = fmaf(cb.x, eqA.x, 1.f); E2 = fmaf(cb.y, eqA.z, 1.f);
                num = fmaf(w.x, E2, w.y * E1);
                aB0 = fmaf(num, frcp(E1 * E2), aB0);
                E1 = fmaf(cb.x, eqA.y, 1.f); E2 = fmaf(cb.y, eqA.w, 1.f);
                num = fmaf(w.x, E2, w.y * E1);
                aB1 = fmaf(num, frcp(E1 * E2), aB1);
                // pair (h+2, h+3): components .z/.w
                E1 = fmaf(ca.z, eqB.x, 1.f); E2 = fmaf(ca.w, eqB.z, 1.f);
                num = fmaf(w.z, E2, w.w * E1);
                aA0 = fmaf(num, frcp(E1 * E2), aA0);
                E1 = fmaf(ca.z, eqB.y, 1.f); E2 = fmaf(ca.w, eqB.w, 1.f);
                num = fmaf(w.z, E2, w.w * E1);
                aA1 = fmaf(num, frcp(E1 * E2), aA1);
                E1 = fmaf(cb.z, eqB.x, 1.f); E2 = fmaf(cb.w, eqB.z, 1.f);
                num = fmaf(w.z, E2, w.w * E1);
                aB0 = fmaf(num, frcp(E1 * E2), aB0);
                E1 = fmaf(cb.z, eqB.y, 1.f); E2 = fmaf(cb.w, eqB.w, 1.f);
                num = fmaf(w.z, E2, w.w * E1);
                aB1 = fmaf(num, frcp(E1 * E2), aB1);
            }
            // exp (no max subtraction needed: |score| <= ~18)
            float pA0 = fex2(aA0 * LOG2E);
            float pA1 = fex2(aA1 * LOG2E);
            float pB0 = fex2(aB0 * LOG2E);
            float pB1 = fex2(aB1 * LOG2E);
            *(float4*)&s_scores[k0 * 2] = make_float4(pA0, pA1, pB0, pB1);
            bool two = (k0 + 1 < len);
            if (!two) { pB0 = 0.f; pB1 = 0.f; }   // guard odd len tail
            sum0 += pA0 + pB0;
            sum1 += pA1 + pB1;
        }
    }
    // NOTE: if len is odd, s_scores[len] was written but AV reads only k<len.

    // ---- denominator reduction ----
    int warp = tid >> 5, lane = tid & 31;
    for (int o = 16; o > 0; o >>= 1) {
        sum0 += __shfl_xor_sync(0xffffffffu, sum0, o);
        sum1 += __shfl_xor_sync(0xffffffffu, sum1, o);
    }
    if (lane == 0) { s_red[warp][0] = sum0; s_red[warp][1] = sum1; }
    __syncthreads();
    if (tid < 2) {
        float s = 0.f;
        for (int w = 0; w < 8; w++) s += s_red[w][tid];
        s_rden[tid] = frcp(s);
    }
    __syncthreads();

    // ---- attn @ V  (8 k-groups x 32 lanes, float4 V loads) ----
    int g = warp;              // k-group = warp (0..7)
    int l = lane;              // v quad index: v0 = 4*l
    float4 a0 = make_float4(0.f, 0.f, 0.f, 0.f);   // q0, 4 v
    float4 a1 = make_float4(0.f, 0.f, 0.f, 0.f);   // q1, 4 v
    const float4* Vp = (const float4*)(values + (size_t)b * KK * DVV) + l;
    for (int k = g; k < len; k += 8) {
        float2 p = *(const float2*)&s_scores[k * 2];
        float4 v = Vp[k * (DVV / 4)];
        a0.x = fmaf(p.x, v.x, a0.x); a0.y = fmaf(p.x, v.y, a0.y);
        a0.z = fmaf(p.x, v.z, a0.z); a0.w = fmaf(p.x, v.w, a0.w);
        a1.x = fmaf(p.y, v.x, a1.x); a1.y = fmaf(p.y, v.y, a1.y);
        a1.z = fmaf(p.y, v.z, a1.z); a1.w = fmaf(p.y, v.w, a1.w);
    }
    *(float4*)&s_part[g][0][4 * l] = a0;
    *(float4*)&s_part[g][1][4 * l] = a1;
    __syncthreads();

    {
        int qq = tid >> 7;
        int v  = tid & 127;
        float rd = s_rden[qq];
        float o = ((s_part[0][qq][v] + s_part[1][qq][v])
                 + (s_part[2][qq][v] + s_part[3][qq][v]))
                + ((s_part[4][qq][v] + s_part[5][qq][v])
                 + (s_part[6][qq][v] + s_part[7][qq][v]));
        out[((size_t)(b * QQ + q0 + qq)) * DVV + v] = o * rd;
    }
}

extern "C" void kernel_launch(void* const* d_in, const int* in_sizes, int n_in,
                              void* d_out, int out_size) {
    const float* queries = (const float*)d_in[0];   // [8,256,256]
    const float* keys    = (const float*)d_in[1];   // [8,1024,256]
    const float* values  = (const float*)d_in[2];   // [8,1024,128]
    const int*   vlens   = (const int*)  d_in[3];   // [8]
    const float* W_q     = (const float*)d_in[4];   // [256,128]
    const float* W_k     = (const float*)d_in[5];   // [256,128]
    const float* w_v     = (const float*)d_in[6];   // [128]
    float* out = (float*)d_out;                     // [8,256,128]

    proj_kernel<<<(BB * QQ + BB * KK) / PR, 256>>>(queries, keys, W_q, W_k);
    attn_kernel<<<BB * (QQ / 2), 256>>>(values, vlens, w_v, out);
}

// round 13
// speedup vs baseline: 1.8089x; 1.0316x over previous
#include <cuda_runtime.h>

#define BB   8
#define QQ   256
#define KK   1024
#define DD   256
#define HH   128
#define DVV  128
#define LOG2E 1.44269504088896340736f

typedef unsigned long long u64;

// Scratch (allocation-free: device globals)
__device__ float g_Eq [BB * QQ * HH];        // [b][q][h]   = exp(2*qproj)
__device__ float g_Ek4[BB * (HH/4) * KK * 4];// [b][h/4][k][4] = exp(2*kproj)

__device__ __forceinline__ float frcp(float x) {
    float r; asm("rcp.approx.f32 %0, %1;" : "=f"(r) : "f"(x)); return r;
}
__device__ __forceinline__ float fex2(float x) {
    float r; asm("ex2.approx.f32 %0, %1;" : "=f"(r) : "f"(x)); return r;
}
// ---- f32x2 packed helpers (FFMA2: PTX-only, full-rate, IEEE per lane) ----
__device__ __forceinline__ u64 ffma2(u64 a, u64 b, u64 c) {
    u64 d; asm("fma.rn.f32x2 %0, %1, %2, %3;" : "=l"(d) : "l"(a), "l"(b), "l"(c));
    return d;
}
__device__ __forceinline__ u64 fmul2(u64 a, u64 b) {
    u64 d; asm("mul.rn.f32x2 %0, %1, %2;" : "=l"(d) : "l"(a), "l"(b));
    return d;
}
__device__ __forceinline__ u64 dup2(float x) {
    u64 d; asm("mov.b64 %0, {%1, %1};" : "=l"(d) : "f"(x));
    return d;
}
__device__ __forceinline__ float2 unpk(u64 a) {
    float2 f; asm("mov.b64 {%0, %1}, %2;" : "=f"(f.x), "=f"(f.y) : "l"(a));
    return f;
}
__device__ __forceinline__ u64 pk(float x, float y) {
    u64 d; asm("mov.b64 %0, {%1, %2};" : "=l"(d) : "f"(x), "f"(y));
    return d;
}

// ---------------------------------------------------------------------------
// Kernel 1: merged projection + exp. 16 rows per block, 256 threads:
// tid&127 = output column h, tid>>7 = row-half. W native [d][h] (coalesced),
// depth-1 prefetch. Inner loop f32x2-packed over d-pairs (FMA pipe halved).
// ---------------------------------------------------------------------------
#define PR 16
__global__ __launch_bounds__(256)
void proj_kernel(const float* __restrict__ Q, const float* __restrict__ Kx,
                 const float* __restrict__ Wq, const float* __restrict__ Wk) {
    __shared__ __align__(16) float xs[PR][DD];     // 16 input rows (16 KB)
    __shared__ float es[HH][PR + 1];               // padded transpose buffer
    int blk  = blockIdx.x;
    bool isK = blk >= (BB * QQ) / PR;              // >= 128
    int rowbase = isK ? (blk - (BB * QQ) / PR) * PR : blk * PR;
    const float* X = isK ? Kx : Q;
    const float* W = isK ? Wk : Wq;
    int tid  = threadIdx.x;
    int h    = tid & 127;                          // output column
    int half = tid >> 7;                           // row-half: 0 or 1
    int r0   = half * 8;                           // first of 8 rows

    {   // coalesced float4 row load (256 threads)
        const float4* Xp = (const float4*)(X + (size_t)rowbase * DD);
        float4* xsp = (float4*)xs;
        for (int i = tid; i < PR * DD / 4; i += 256) xsp[i] = Xp[i];
    }
    __syncthreads();

    u64 acc2[8];
#pragma unroll
    for (int r = 0; r < 8; r++) acc2[r] = 0ull;

    const float* Wp = W + h;
    float w0 = Wp[0 * HH], w1 = Wp[1 * HH], w2 = Wp[2 * HH], w3 = Wp[3 * HH];
    for (int d4 = 0; d4 < DD / 4; d4++) {
        u64 cp01 = pk(w0, w1), cp23 = pk(w2, w3);
        if (d4 + 1 < DD / 4) {                     // prefetch next W quad
            const float* Wn = Wp + (d4 + 1) * 4 * HH;
            w0 = Wn[0 * HH]; w1 = Wn[1 * HH]; w2 = Wn[2 * HH]; w3 = Wn[3 * HH];
        }
        int d = d4 * 4;
#pragma unroll
        for (int r = 0; r < 8; r++) {
            ulonglong2 x2 = *(const ulonglong2*)&xs[r0 + r][d]; // LDS.128
            acc2[r] = ffma2(x2.x, cp01, acc2[r]);
            acc2[r] = ffma2(x2.y, cp23, acc2[r]);
        }
    }

    if (!isK) {
#pragma unroll
        for (int r = 0; r < 8; r++) {
            float2 f = unpk(acc2[r]);
            g_Eq[(rowbase + r0 + r) * HH + h] =
                fex2((f.x + f.y) * (2.0f * LOG2E));
        }
    } else {
#pragma unroll
        for (int r = 0; r < 8; r++) {
            float2 f = unpk(acc2[r]);
            es[h][r0 + r] = fex2((f.x + f.y) * (2.0f * LOG2E));
        }
        __syncthreads();
        int b  = rowbase >> 10;
        int k0 = rowbase & 1023;
        // interleaved store: [hq][k][h%4], consecutive i -> consecutive addr
        for (int i = tid; i < HH * PR; i += 256) {
            int hq = i >> 6;              // 64 = PR*4 elements per h-quad
            int r  = (i >> 2) & (PR - 1);
            int h2 = i & 3;
            g_Ek4[(((size_t)b * (HH/4) + hq) * KK + k0 + r) * 4 + h2]
                = es[hq * 4 + h2][r];
        }
    }
}

// ---------------------------------------------------------------------------
// Kernel 2: fused scores + exp + softmax-denominator + attn@V.
// Block = (b, tile of 2 q-rows), 1024 blocks, 256 threads.
//   s = sum_h (-2 w_h) * rcp(1 + Eq*Ek)   (wsum cancels in softmax)
// |s| <= ~18 -> exp without max subtraction is fp32-safe.
// LOAD STRUCTURE FROZEN (R5: LDG.128 interleaved quads, indexed depth-2
// prefetch). Arithmetic repacked f32x2 over the (q0,q1) pair: s_eq[h] in
// smem IS the 64-bit pack; accumulators/E/num/P packed; only rcp unpacks.
// ---------------------------------------------------------------------------
#define ONE2 0x3f8000003f800000ull

// one h-pair x one k, both q packed: acc += num * rcp(E1*E2)
#define UNIT(ekA_s, ekB_s, eqA, eqB, wA, wB, accp) do {            \
    u64 ek1_ = dup2(ekA_s), ek2_ = dup2(ekB_s);                    \
    u64 E1_ = ffma2(ek1_, eqA, ONE2);                              \
    u64 E2_ = ffma2(ek2_, eqB, ONE2);                              \
    u64 num_ = ffma2(wA, E2_, fmul2(wB, E1_));                     \
    float2 pf_ = unpk(fmul2(E1_, E2_));                            \
    u64 R_ = pk(frcp(pf_.x), frcp(pf_.y));                         \
    accp = ffma2(num_, R_, accp);                                  \
} while (0)

__global__ __launch_bounds__(256)
void attn_kernel(const float* __restrict__ values,
                 const int*   __restrict__ valid_lens,
                 const float* __restrict__ w_v,
                 float*       __restrict__ out) {
    __shared__ __align__(16) float s_eq[HH][2];        // [h] -> (q0,q1) pack
    __shared__ __align__(16) float2 s_w2d[HH];         // dup(-2*w_v[h])
    __shared__ __align__(16) float s_scores[KK * 2];   // exp'ed probs [k][q]
    __shared__ __align__(16) float s_part[8][2][DVV];  // [kgroup][q][v]
    __shared__ float s_red[8][2];
    __shared__ float s_rden[2];

    int b  = blockIdx.x & 7;
    int q0 = (blockIdx.x >> 3) * 2;
    int tid = threadIdx.x;
    int len = valid_lens[b];

    if (tid < HH) {
        float w = -2.0f * w_v[tid];
        s_w2d[tid] = make_float2(w, w);
    }
    if (tid < 2 * HH) {
        int qq = tid >> 7, h = tid & 127;
        s_eq[h][qq] = g_Eq[((b * QQ) + q0 + qq) * HH + h];
    }
    __syncthreads();

    float sum0 = 0.f, sum1 = 0.f;   // denominator partials (q0, q1)

    // ---- main loop: scores + exp (k chunks of 512, 2 k per thread) ----
    for (int kbase = 0; kbase < len; kbase += 512) {
        int k0 = kbase + tid * 2;
        if (k0 < len) {
            u64 aA = 0ull, aB = 0ull;       // k0 / k0+1, (q0,q1) packed
            // float4 view: index = hq*KK + k
            const float4* ek4 = (const float4*)g_Ek4 + (size_t)b * (HH/4) * KK + k0;
            float4 p0a = ek4[0];            // hq=0, k0
            float4 p0b = ek4[1];            // hq=0, k0+1
            float4 p1a = ek4[KK];           // hq=1, k0
            float4 p1b = ek4[KK + 1];       // hq=1, k0+1
#pragma unroll 2
            for (int hq = 0; hq < HH / 4; hq++) {
                float4 ca = p0a, cb = p0b;
                p0a = p1a; p0b = p1b;
                int hn = (hq + 2) & (HH / 4 - 1);     // wrap: harmless reload
                p1a = ek4[(size_t)hn * KK];
                p1b = ek4[(size_t)hn * KK + 1];
                int h = hq * 4;
                // eq packs: LDS.128 -> (eq_h q0,q1 | eq_h+1 q0,q1)
                float4 eqA4 = *(const float4*)&s_eq[h][0];
                float4 eqB4 = *(const float4*)&s_eq[h + 2][0];
                u64 eq_h  = ((const u64*)&eqA4)[0];
                u64 eq_h1 = ((const u64*)&eqA4)[1];
                u64 eq_h2 = ((const u64*)&eqB4)[0];
                u64 eq_h3 = ((const u64*)&eqB4)[1];
                // w dup packs: LDS.128 -> (dup w_h | dup w_h+1)
                float4 w4a = *(const float4*)&s_w2d[h];
                float4 w4b = *(const float4*)&s_w2d[h + 2];
                u64 w_h  = ((const u64*)&w4a)[0];
                u64 w_h1 = ((const u64*)&w4a)[1];
                u64 w_h2 = ((const u64*)&w4b)[0];
                u64 w_h3 = ((const u64*)&w4b)[1];
                UNIT(ca.x, ca.y, eq_h,  eq_h1, w_h,  w_h1, aA);
                UNIT(cb.x, cb.y, eq_h,  eq_h1, w_h,  w_h1, aB);
                UNIT(ca.z, ca.w, eq_h2, eq_h3, w_h2, w_h3, aA);
                UNIT(cb.z, cb.w, eq_h2, eq_h3, w_h2, w_h3, aB);
            }
            float2 fA = unpk(aA);           // (score k0 q0, k0 q1)
            float2 fB = unpk(aB);
            // exp (no max subtraction needed: |score| <= ~18)
            float pA0 = fex2(fA.x * LOG2E);
            float pA1 = fex2(fA.y * LOG2E);
            float pB0 = fex2(fB.x * LOG2E);
            float pB1 = fex2(fB.y * LOG2E);
            *(float4*)&s_scores[k0 * 2] = make_float4(pA0, pA1, pB0, pB1);
            bool two = (k0 + 1 < len);
            if (!two) { pB0 = 0.f; pB1 = 0.f; }   // guard odd len tail
            sum0 += pA0 + pB0;
            sum1 += pA1 + pB1;
        }
    }
    // NOTE: if len is odd, s_scores[len] was written but AV reads only k<len.

    // ---- denominator reduction ----
    int warp = tid >> 5, lane = tid & 31;
    for (int o = 16; o > 0; o >>= 1) {
        sum0 += __shfl_xor_sync(0xffffffffu, sum0, o);
        sum1 += __shfl_xor_sync(0xffffffffu, sum1, o);
    }
    if (lane == 0) { s_red[warp][0] = sum0; s_red[warp][1] = sum1; }
    __syncthreads();
    if (tid < 2) {
        float s = 0.f;
        for (int w = 0; w < 8; w++) s += s_red[w][tid];
        s_rden[tid] = frcp(s);
    }
    __syncthreads();

    // ---- attn @ V  (8 k-groups x 32 lanes, float4 V loads, f32x2 FMA) ----
    int g = warp;              // k-group = warp (0..7)
    int l = lane;              // v quad index: v0 = 4*l
    u64 a00 = 0ull, a01 = 0ull;   // q0: (v0,v1), (v2,v3)
    u64 a10 = 0ull, a11 = 0ull;   // q1
    const ulonglong2* Vp = (const ulonglong2*)(values + (size_t)b * KK * DVV) + l;
    for (int k = g; k < len; k += 8) {
        float2 p = *(const float2*)&s_scores[k * 2];
        ulonglong2 v = Vp[k * (DVV / 4)];
        u64 px = dup2(p.x), py = dup2(p.y);
        a00 = ffma2(px, v.x, a00); a01 = ffma2(px, v.y, a01);
        a10 = ffma2(py, v.x, a10); a11 = ffma2(py, v.y, a11);
    }
    *(u64*)&s_part[g][0][4 * l]     = a00;
    *(u64*)&s_part[g][0][4 * l + 2] = a01;
    *(u64*)&s_part[g][1][4 * l]     = a10;
    *(u64*)&s_part[g][1][4 * l + 2] = a11;
    __syncthreads();

    {
        int qq = tid >> 7;
        int v  = tid & 127;
        float rd = s_rden[qq];
        float o = ((s_part[0][qq][v] + s_part[1][qq][v])
                 + (s_part[2][qq][v] + s_part[3][qq][v]))
                + ((s_part[4][qq][v] + s_part[5][qq][v])
                 + (s_part[6][qq][v] + s_part[7][qq][v]));
        out[((size_t)(b * QQ + q0 + qq)) * DVV + v] = o * rd;
    }
}

extern "C" void kernel_launch(void* const* d_in, const int* in_sizes, int n_in,
                              void* d_out, int out_size) {
    const float* queries = (const float*)d_in[0];   // [8,256,256]
    const float* keys    = (const float*)d_in[1];   // [8,1024,256]
    const float* values  = (const float*)d_in[2];   // [8,1024,128]
    const int*   vlens   = (const int*)  d_in[3];   // [8]
    const float* W_q     = (const float*)d_in[4];   // [256,128]
    const float* W_k     = (const float*)d_in[5];   // [256,128]
    const float* w_v     = (const float*)d_in[6];   // [128]
    float* out = (float*)d_out;                     // [8,256,128]

    proj_kernel<<<(BB * QQ + BB * KK) / PR, 256>>>(queries, keys, W_q, W_k);
    attn_kernel<<<BB * (QQ / 2), 256>>>(values, vlens, w_v, out);
}

// round 14
// speedup vs baseline: 1.8432x; 1.0189x over previous
#include <cuda_runtime.h>

#define BB   8
#define QQ   256
#define KK   1024
#define DD   256
#define HH   128
#define DVV  128
#define LOG2E 1.44269504088896340736f

typedef unsigned long long u64;

// Scratch (allocation-free: device globals)
// Ek4 layout: per (b,hq) row of KK float4s; granule of 2 float4s (= 1 k-pair):
//   [h0k0, h0k1, h1k0, h1k1 | h2k0, h2k1, h3k0, h3k1]
// so each aligned u64 lane is an (k0,k1) pack for one h.
__device__ float g_Eq [BB * QQ * HH];        // [b][q][h]   = exp(2*qproj)
__device__ float g_Ek4[BB * (HH/4) * KK * 4];// see layout note above

__device__ __forceinline__ float frcp(float x) {
    float r; asm("rcp.approx.f32 %0, %1;" : "=f"(r) : "f"(x)); return r;
}
__device__ __forceinline__ float fex2(float x) {
    float r; asm("ex2.approx.f32 %0, %1;" : "=f"(r) : "f"(x)); return r;
}
// ---- f32x2 packed helpers (FFMA2: PTX-only, full-rate, IEEE per lane) ----
__device__ __forceinline__ u64 ffma2(u64 a, u64 b, u64 c) {
    u64 d; asm("fma.rn.f32x2 %0, %1, %2, %3;" : "=l"(d) : "l"(a), "l"(b), "l"(c));
    return d;
}
__device__ __forceinline__ u64 fmul2(u64 a, u64 b) {
    u64 d; asm("mul.rn.f32x2 %0, %1, %2;" : "=l"(d) : "l"(a), "l"(b));
    return d;
}
__device__ __forceinline__ u64 dup2(float x) {
    u64 d; asm("mov.b64 %0, {%1, %1};" : "=l"(d) : "f"(x));
    return d;
}
__device__ __forceinline__ float2 unpk(u64 a) {
    float2 f; asm("mov.b64 {%0, %1}, %2;" : "=f"(f.x), "=f"(f.y) : "l"(a));
    return f;
}
__device__ __forceinline__ u64 pk(float x, float y) {
    u64 d; asm("mov.b64 %0, {%1, %2};" : "=l"(d) : "f"(x), "f"(y));
    return d;
}

// ---------------------------------------------------------------------------
// Kernel 1: merged projection + exp. 16 rows per block, 256 threads:
// tid&127 = output column h, tid>>7 = row-half. W native [d][h] (coalesced),
// depth-1 prefetch, f32x2-packed inner loop. K store uses the k-pair layout.
// ---------------------------------------------------------------------------
#define PR 16
__global__ __launch_bounds__(256)
void proj_kernel(const float* __restrict__ Q, const float* __restrict__ Kx,
                 const float* __restrict__ Wq, const float* __restrict__ Wk) {
    __shared__ __align__(16) float xs[PR][DD];     // 16 input rows (16 KB)
    __shared__ float es[HH][PR + 1];               // padded transpose buffer
    int blk  = blockIdx.x;
    bool isK = blk >= (BB * QQ) / PR;              // >= 128
    int rowbase = isK ? (blk - (BB * QQ) / PR) * PR : blk * PR;
    const float* X = isK ? Kx : Q;
    const float* W = isK ? Wk : Wq;
    int tid  = threadIdx.x;
    int h    = tid & 127;                          // output column
    int half = tid >> 7;                           // row-half: 0 or 1
    int r0   = half * 8;                           // first of 8 rows

    {   // coalesced float4 row load (256 threads)
        const float4* Xp = (const float4*)(X + (size_t)rowbase * DD);
        float4* xsp = (float4*)xs;
        for (int i = tid; i < PR * DD / 4; i += 256) xsp[i] = Xp[i];
    }
    __syncthreads();

    u64 acc2[8];
#pragma unroll
    for (int r = 0; r < 8; r++) acc2[r] = 0ull;

    const float* Wp = W + h;
    float w0 = Wp[0 * HH], w1 = Wp[1 * HH], w2 = Wp[2 * HH], w3 = Wp[3 * HH];
    for (int d4 = 0; d4 < DD / 4; d4++) {
        u64 cp01 = pk(w0, w1), cp23 = pk(w2, w3);
        if (d4 + 1 < DD / 4) {                     // prefetch next W quad
            const float* Wn = Wp + (d4 + 1) * 4 * HH;
            w0 = Wn[0 * HH]; w1 = Wn[1 * HH]; w2 = Wn[2 * HH]; w3 = Wn[3 * HH];
        }
        int d = d4 * 4;
#pragma unroll
        for (int r = 0; r < 8; r++) {
            ulonglong2 x2 = *(const ulonglong2*)&xs[r0 + r][d]; // LDS.128
            acc2[r] = ffma2(x2.x, cp01, acc2[r]);
            acc2[r] = ffma2(x2.y, cp23, acc2[r]);
        }
    }

    if (!isK) {
#pragma unroll
        for (int r = 0; r < 8; r++) {
            float2 f = unpk(acc2[r]);
            g_Eq[(rowbase + r0 + r) * HH + h] =
                fex2((f.x + f.y) * (2.0f * LOG2E));
        }
    } else {
#pragma unroll
        for (int r = 0; r < 8; r++) {
            float2 f = unpk(acc2[r]);
            es[h][r0 + r] = fex2((f.x + f.y) * (2.0f * LOG2E));
        }
        __syncthreads();
        int b  = rowbase >> 10;
        int k0 = rowbase & 1023;
        // k-pair interleaved store: float idx within (row,k-pair) granule is
        // h2*2 + (k&1); granule base = (row*KK + k0 + (r&~1)) * 4.
        for (int i = tid; i < HH * PR; i += 256) {
            int hq = i >> 6;              // 64 = PR*4 elements per h-quad
            int r  = (i >> 2) & (PR - 1);
            int h2 = i & 3;
            size_t fi = (((size_t)b * (HH/4) + hq) * KK + k0 + (r & ~1)) * 4
                      + h2 * 2 + (r & 1);
            g_Ek4[fi] = es[hq * 4 + h2][r];
        }
    }
}

// ---------------------------------------------------------------------------
// Kernel 2: fused scores + exp + softmax-denominator + attn@V.
// Block = (b, tile of 2 q-rows), 1024 blocks, 256 threads.
//   s = sum_h (-2 w_h) * rcp(1 + Eq*Ek)   (wsum cancels in softmax)
// LOAD ADDRESSES BYTE-IDENTICAL to the frozen R5 structure (same float4
// indices, same indexed depth-2 prefetch). Changes vs R13:
//  - k-pair granule layout: each loaded u64 lane is an (k0,k1) pack for one
//    h -> zero dup2 MOVs in the loop (eq dups pre-built in smem).
//  - quad-h rcp: n12/P12 + n34/P34 = (n12*P34+n34*P12)*rcp(P12*P34)
//    -> 4 MUFU/iter instead of 8. Product of 4 E's <= ~e^40 realistic,
//    overflow needs ~15-sigma; all E >= 1.
// ---------------------------------------------------------------------------
#define ONE2 0x3f8000003f800000ull

__global__ __launch_bounds__(256)
void attn_kernel(const float* __restrict__ values,
                 const int*   __restrict__ valid_lens,
                 const float* __restrict__ w_v,
                 float*       __restrict__ out) {
    __shared__ __align__(16) float2 s_eqd[2][HH];      // dup'ed eq, per q
    __shared__ __align__(16) float2 s_w2d[HH];         // dup(-2*w_v[h])
    __shared__ __align__(16) float s_scores[KK * 2];   // exp'ed probs [k][q]
    __shared__ __align__(16) float s_part[8][2][DVV];  // [kgroup][q][v]
    __shared__ float s_red[8][2];
    __shared__ float s_rden[2];

    int b  = blockIdx.x & 7;
    int q0 = (blockIdx.x >> 3) * 2;
    int tid = threadIdx.x;
    int len = valid_lens[b];

    if (tid < HH) {
        float w = -2.0f * w_v[tid];
        s_w2d[tid] = make_float2(w, w);
    }
    if (tid < 2 * HH) {
        int qq = tid >> 7, h = tid & 127;
        float v = g_Eq[((b * QQ) + q0 + qq) * HH + h];
        s_eqd[qq][h] = make_float2(v, v);
    }
    __syncthreads();

    float sum0 = 0.f, sum1 = 0.f;   // denominator partials (q0, q1)

    // ---- main loop: scores + exp (k chunks of 512, 2 k per thread) ----
    for (int kbase = 0; kbase < len; kbase += 512) {
        int k0 = kbase + tid * 2;
        if (k0 < len) {
            u64 accA = 0ull, accB = 0ull;   // (k0,k1) packs for q0 / q1
            // float4 view: same indices as frozen structure
            const float4* ek4 = (const float4*)g_Ek4 + (size_t)b * (HH/4) * KK + k0;
            float4 p0a = ek4[0];            // hq, h0/h1 packs
            float4 p0b = ek4[1];            // hq, h2/h3 packs
            float4 p1a = ek4[KK];           // hq+1
            float4 p1b = ek4[KK + 1];
#pragma unroll 2
            for (int hq = 0; hq < HH / 4; hq++) {
                float4 ca = p0a, cb = p0b;
                p0a = p1a; p0b = p1b;
                int hn = (hq + 2) & (HH / 4 - 1);     // wrap: harmless reload
                p1a = ek4[(size_t)hn * KK];
                p1b = ek4[(size_t)hn * KK + 1];
                int h = hq * 4;
                // ek (k0,k1) packs per h — straight from the loads, no dup
                u64 ek0 = ((const u64*)&ca)[0];
                u64 ek1 = ((const u64*)&ca)[1];
                u64 ek2 = ((const u64*)&cb)[0];
                u64 ek3 = ((const u64*)&cb)[1];
                // w dups (LDS.128 x2)
                float4 w4a = *(const float4*)&s_w2d[h];
                float4 w4b = *(const float4*)&s_w2d[h + 2];
                u64 w0 = ((const u64*)&w4a)[0];
                u64 w1 = ((const u64*)&w4a)[1];
                u64 w2 = ((const u64*)&w4b)[0];
                u64 w3 = ((const u64*)&w4b)[1];
#pragma unroll
                for (int qq = 0; qq < 2; qq++) {
                    // eq dups (LDS.128 x2 per q)
                    float4 e4a = *(const float4*)&s_eqd[qq][h];
                    float4 e4b = *(const float4*)&s_eqd[qq][h + 2];
                    u64 e0 = ((const u64*)&e4a)[0];
                    u64 e1 = ((const u64*)&e4a)[1];
                    u64 e2 = ((const u64*)&e4b)[0];
                    u64 e3 = ((const u64*)&e4b)[1];
                    u64 E1 = ffma2(ek0, e0, ONE2);
                    u64 E2 = ffma2(ek1, e1, ONE2);
                    u64 E3 = ffma2(ek2, e2, ONE2);
                    u64 E4 = ffma2(ek3, e3, ONE2);
                    u64 P12 = fmul2(E1, E2);
                    u64 P34 = fmul2(E3, E4);
                    u64 n12 = ffma2(w0, E2, fmul2(w1, E1));
                    u64 n34 = ffma2(w2, E4, fmul2(w3, E3));
                    u64 nt  = ffma2(n12, P34, fmul2(n34, P12));
                    float2 pf = unpk(fmul2(P12, P34));
                    u64 R = pk(frcp(pf.x), frcp(pf.y));
                    if (qq == 0) accA = ffma2(nt, R, accA);
                    else         accB = ffma2(nt, R, accB);
                }
            }
            float2 f0 = unpk(accA);         // (score k0 q0, score k1 q0)
            float2 f1 = unpk(accB);         // (score k0 q1, score k1 q1)
            // exp (no max subtraction needed: |score| <= ~18)
            float pA0 = fex2(f0.x * LOG2E);
            float pA1 = fex2(f1.x * LOG2E);
            float pB0 = fex2(f0.y * LOG2E);
            float pB1 = fex2(f1.y * LOG2E);
            *(float4*)&s_scores[k0 * 2] = make_float4(pA0, pA1, pB0, pB1);
            bool two = (k0 + 1 < len);
            if (!two) { pB0 = 0.f; pB1 = 0.f; }   // guard odd len tail
            sum0 += pA0 + pB0;
            sum1 += pA1 + pB1;
        }
    }
    // NOTE: if len is odd, s_scores[len] was written but AV reads only k<len.

    // ---- denominator reduction ----
    int warp = tid >> 5, lane = tid & 31;
    for (int o = 16; o > 0; o >>= 1) {
        sum0 += __shfl_xor_sync(0xffffffffu, sum0, o);
        sum1 += __shfl_xor_sync(0xffffffffu, sum1, o);
    }
    if (lane == 0) { s_red[warp][0] = sum0; s_red[warp][1] = sum1; }
    __syncthreads();
    if (tid < 2) {
        float s = 0.f;
        for (int w = 0; w < 8; w++) s += s_red[w][tid];
        s_rden[tid] = frcp(s);
    }
    __syncthreads();

    // ---- attn @ V  (8 k-groups x 32 lanes, float4 V loads, f32x2 FMA) ----
    int g = warp;              // k-group = warp (0..7)
    int l = lane;              // v quad index: v0 = 4*l
    u64 a00 = 0ull, a01 = 0ull;   // q0: (v0,v1), (v2,v3)
    u64 a10 = 0ull, a11 = 0ull;   // q1
    const ulonglong2* Vp = (const ulonglong2*)(values + (size_t)b * KK * DVV) + l;
    for (int k = g; k < len; k += 8) {
        float2 p = *(const float2*)&s_scores[k * 2];
        ulonglong2 v = Vp[k * (DVV / 4)];
        u64 px = dup2(p.x), py = dup2(p.y);
        a00 = ffma2(px, v.x, a00); a01 = ffma2(px, v.y, a01);
        a10 = ffma2(py, v.x, a10); a11 = ffma2(py, v.y, a11);
    }
    *(u64*)&s_part[g][0][4 * l]     = a00;
    *(u64*)&s_part[g][0][4 * l + 2] = a01;
    *(u64*)&s_part[g][1][4 * l]     = a10;
    *(u64*)&s_part[g][1][4 * l + 2] = a11;
    __syncthreads();

    {
        int qq = tid >> 7;
        int v  = tid & 127;
        float rd = s_rden[qq];
        float o = ((s_part[0][qq][v] + s_part[1][qq][v])
                 + (s_part[2][qq][v] + s_part[3][qq][v]))
                + ((s_part[4][qq][v] + s_part[5][qq][v])
                 + (s_part[6][qq][v] + s_part[7][qq][v]));
        out[((size_t)(b * QQ + q0 + qq)) * DVV + v] = o * rd;
    }
}

extern "C" void kernel_launch(void* const* d_in, const int* in_sizes, int n_in,
                              void* d_out, int out_size) {
    const float* queries = (const float*)d_in[0];   // [8,256,256]
    const float* keys    = (const float*)d_in[1];   // [8,1024,256]
    const float* values  = (const float*)d_in[2];   // [8,1024,128]
    const int*   vlens   = (const int*)  d_in[3];   // [8]
    const float* W_q     = (const float*)d_in[4];   // [256,128]
    const float* W_k     = (const float*)d_in[5];   // [256,128]
    const float* w_v     = (const float*)d_in[6];   // [128]
    float* out = (float*)d_out;                     // [8,256,128]

    proj_kernel<<<(BB * QQ + BB * KK) / PR, 256>>>(queries, keys, W_q, W_k);
    attn_kernel<<<BB * (QQ / 2), 256>>>(values, vlens, w_v, out);
}